// round 1
// baseline (speedup 1.0000x reference)
#include <cuda_runtime.h>
#include <cuda_bf16.h>

// DistortionLoss: per-ray NeRF distortion loss.
//   bins = (z - near)/(far - near); m_k = 0.5*(bins_k + bins_{k+1})
//   loss = sum_ij w_i w_j |m_i - m_j| + (1/3) sum_i w_i^2 (bins_{k+1}-bins_k)
// z sorted => midpoints sorted => pairwise term = 2*sum_i w_i*(m_i*Sw_excl - Swm_excl)
// One warp per ray, 4 elements per lane, warp shuffle scans. Pure streaming: HBM-bound.

#define FULL 0xFFFFFFFFu

__global__ void __launch_bounds__(256) distortion_loss_kernel(
    const float* __restrict__ w,     // [R,128]
    const float* __restrict__ z,     // [R,129]
    const float* __restrict__ nearp, // [R]
    const float* __restrict__ farp,  // [R]
    float* __restrict__ out,         // [R]
    int R)
{
    const int warp = (blockIdx.x * blockDim.x + threadIdx.x) >> 5;
    const int lane = threadIdx.x & 31;
    if (warp >= R) return;

    const float* wr = w + (size_t)warp * 128;
    const float* zr = z + (size_t)warp * 129;

    const float nr  = __ldg(nearp + warp);
    const float fr  = __ldg(farp  + warp);
    const float inv = 1.0f / (fr - nr);

    // weights: one float4 per lane (rows are 512B, 16B-aligned)
    float4 w4 = reinterpret_cast<const float4*>(wr)[lane];
    float wv[4] = {w4.x, w4.y, w4.z, w4.w};

    // z: 5 scalar loads (elements 4*lane .. 4*lane+4); 129-stride rows are not
    // float4-alignable. Coalesced within the warp.
    float zv[5];
    #pragma unroll
    for (int i = 0; i < 5; i++) zv[i] = zr[4 * lane + i];

    float b[5];
    #pragma unroll
    for (int i = 0; i < 5; i++) b[i] = (zv[i] - nr) * inv;

    float m[4], wm[4];
    #pragma unroll
    for (int k = 0; k < 4; k++) {
        m[k]  = 0.5f * (b[k] + b[k + 1]);
        wm[k] = wv[k] * m[k];
    }

    // local inclusive sums of this lane's 4 elements
    float cw[4], cwm[4];
    cw[0]  = wv[0];  cwm[0] = wm[0];
    #pragma unroll
    for (int k = 1; k < 4; k++) {
        cw[k]  = cw[k - 1]  + wv[k];
        cwm[k] = cwm[k - 1] + wm[k];
    }
    const float tw  = cw[3];   // lane total of w
    const float twm = cwm[3];  // lane total of w*m

    // warp inclusive scan of lane totals (two scans share the shuffle ladder)
    float pw = tw, pwm = twm;
    #pragma unroll
    for (int off = 1; off < 32; off <<= 1) {
        float aw  = __shfl_up_sync(FULL, pw,  off);
        float awm = __shfl_up_sync(FULL, pwm, off);
        if (lane >= off) { pw += aw; pwm += awm; }
    }
    const float base_w  = pw  - tw;   // exclusive base for this lane
    const float base_wm = pwm - twm;

    // accumulate: 2*w_i*(m_i*Sw_excl - Swm_excl) + (1/3)*w_i^2*(b_{i+1}-b_i)
    float acc = 0.0f;
    #pragma unroll
    for (int k = 0; k < 4; k++) {
        const float ew  = base_w  + (k ? cw[k - 1]  : 0.0f);
        const float ewm = base_wm + (k ? cwm[k - 1] : 0.0f);
        acc += 2.0f * wv[k] * (m[k] * ew - ewm);
        acc += (1.0f / 3.0f) * wv[k] * wv[k] * (b[k + 1] - b[k]);
    }

    // warp reduction
    #pragma unroll
    for (int off = 16; off > 0; off >>= 1)
        acc += __shfl_down_sync(FULL, acc, off);

    if (lane == 0) out[warp] = acc;
}

extern "C" void kernel_launch(void* const* d_in, const int* in_sizes, int n_in,
                              void* d_out, int out_size)
{
    const float* w    = (const float*)d_in[0]; // weights [R,128,1]
    const float* z    = (const float*)d_in[1]; // z_vals  [R,129]
    const float* nr   = (const float*)d_in[2]; // near    [R,1]
    const float* fr   = (const float*)d_in[3]; // far     [R,1]
    float*       out  = (float*)d_out;         // [R,1]

    const int R = in_sizes[0] / 128;           // 8192
    const int threads = 256;                   // 8 warps -> 8 rays per block
    const int blocks  = (R * 32 + threads - 1) / threads;
    distortion_loss_kernel<<<blocks, threads>>>(w, z, nr, fr, out, R);
}

// round 2
// speedup vs baseline: 1.0045x; 1.0045x over previous
#include <cuda_runtime.h>
#include <cuda_bf16.h>
#include <cstdint>

// DistortionLoss: per-ray NeRF distortion loss, O(N) via sorted-midpoint prefix sums.
//   loss = 2*sum_i w_i*(m_i*Sw_excl(i) - Swm_excl(i)) + (1/3)*sum_i w_i^2*(b_{i+1}-b_i)
//
// R2 change: z is block-staged through shared memory with cp.async float4 copies.
// A block of 8 rays covers z[1032*b .. 1032*b+1032) -- 1032 % 4 == 0, so the
// region is exactly 258 aligned float4s. This kills the 5x-overlapping scalar
// LDG pattern that made L1 the top pipe (19.7%) in R1.

#define FULL 0xFFFFFFFFu

__device__ __forceinline__ void cp_async16(void* smem_dst, const void* gmem_src) {
    uint32_t s = (uint32_t)__cvta_generic_to_shared(smem_dst);
    asm volatile("cp.async.cg.shared.global [%0], [%1], 16;\n" :: "r"(s), "l"(gmem_src));
}

__global__ void __launch_bounds__(256) distortion_loss_kernel(
    const float* __restrict__ w,     // [R,128]
    const float* __restrict__ z,     // [R,129]
    const float* __restrict__ nearp, // [R]
    const float* __restrict__ farp,  // [R]
    float* __restrict__ out,         // [R]
    int R)
{
    __shared__ float zsh[8 * 129];   // 1032 floats, contiguous (no padding)

    const int tid  = threadIdx.x;
    const int wrp  = tid >> 5;       // 0..7: ray within block
    const int lane = tid & 31;
    const int ray  = blockIdx.x * 8 + wrp;

    // ---- stage z: 258 aligned float4s per block, cp.async (in flight first) ----
    const size_t zbase = (size_t)blockIdx.x * 1032;
    const size_t ztotal = (size_t)R * 129;
    {
        const float* zblk = z + zbase;
        // threads 0..255 copy float4 #tid; threads 0,1 also copy #256,#257
        size_t rem4 = (ztotal - zbase) >> 2;             // float4s available (tail-safe)
        if (tid < 258 && (size_t)tid < rem4)
            cp_async16(&zsh[4 * tid], zblk + 4 * tid);
        if (tid < 2 && (size_t)(256 + tid) < rem4 && (256 + tid) < 258)
            cp_async16(&zsh[4 * (256 + tid)], zblk + 4 * (256 + tid));
        asm volatile("cp.async.commit_group;\n" ::: "memory");
    }

    const bool active = (ray < R);

    // ---- w: one float4 per lane (rows are 512B, 16B-aligned), issued while z flies ----
    float4 w4 = make_float4(0.f, 0.f, 0.f, 0.f);
    float nr = 0.f, fr = 1.f;
    if (active) {
        w4 = reinterpret_cast<const float4*>(w + (size_t)ray * 128)[lane];
        nr = __ldg(nearp + ray);
        fr = __ldg(farp  + ray);
    }
    const float inv = 1.0f / (fr - nr);
    float wv[4] = {w4.x, w4.y, w4.z, w4.w};

    asm volatile("cp.async.wait_group 0;\n" ::: "memory");
    __syncthreads();

    // ---- z from smem: 5 scalars per lane (4-way bank phases, cheap) ----
    const float* zrow = zsh + wrp * 129;
    float b[5];
    #pragma unroll
    for (int i = 0; i < 5; i++) b[i] = (zrow[4 * lane + i] - nr) * inv;

    float m[4], wm[4];
    #pragma unroll
    for (int k = 0; k < 4; k++) {
        m[k]  = 0.5f * (b[k] + b[k + 1]);
        wm[k] = wv[k] * m[k];
    }

    // local inclusive sums over the lane's 4 elements
    float cw[4], cwm[4];
    cw[0] = wv[0]; cwm[0] = wm[0];
    #pragma unroll
    for (int k = 1; k < 4; k++) {
        cw[k]  = cw[k - 1]  + wv[k];
        cwm[k] = cwm[k - 1] + wm[k];
    }
    const float tw = cw[3], twm = cwm[3];

    // warp inclusive scan of lane totals (shared shuffle ladder)
    float pw = tw, pwm = twm;
    #pragma unroll
    for (int off = 1; off < 32; off <<= 1) {
        float aw  = __shfl_up_sync(FULL, pw,  off);
        float awm = __shfl_up_sync(FULL, pwm, off);
        if (lane >= off) { pw += aw; pwm += awm; }
    }
    const float base_w  = pw  - tw;
    const float base_wm = pwm - twm;

    float acc = 0.0f;
    #pragma unroll
    for (int k = 0; k < 4; k++) {
        const float ew  = base_w  + (k ? cw[k - 1]  : 0.0f);
        const float ewm = base_wm + (k ? cwm[k - 1] : 0.0f);
        acc += 2.0f * wv[k] * (m[k] * ew - ewm);
        acc += (1.0f / 3.0f) * wv[k] * wv[k] * (b[k + 1] - b[k]);
    }

    // warp reduction
    #pragma unroll
    for (int off = 16; off > 0; off >>= 1)
        acc += __shfl_down_sync(FULL, acc, off);

    if (active && lane == 0) out[ray] = acc;
}

extern "C" void kernel_launch(void* const* d_in, const int* in_sizes, int n_in,
                              void* d_out, int out_size)
{
    const float* w   = (const float*)d_in[0]; // weights [R,128,1]
    const float* z   = (const float*)d_in[1]; // z_vals  [R,129]
    const float* nr  = (const float*)d_in[2]; // near    [R,1]
    const float* fr  = (const float*)d_in[3]; // far     [R,1]
    float*       out = (float*)d_out;         // [R,1]

    const int R = in_sizes[0] / 128;          // 8192
    const int blocks = (R + 7) / 8;           // 8 rays per 256-thread block
    distortion_loss_kernel<<<blocks, 256>>>(w, z, nr, fr, out, R);
}

// round 3
// speedup vs baseline: 1.0625x; 1.0577x over previous
#include <cuda_runtime.h>
#include <cuda_bf16.h>

// DistortionLoss, O(N) via sorted-midpoint prefix sums, minimal-instruction form.
//
// Factorized math (near/inv pulled out of the inner loop):
//   s_k  = z_k + z_{k+1}          (2*midpoint, un-normalized)
//   dz_k = z_{k+1} - z_k
//   loss = inv * [ sum_k w_k*(s_k*W_<k - WS_<k)  +  (1/3)*sum_k w_k^2*dz_k ]
// where inv = 1/(far-near), W_< / WS_< are exclusive prefix sums of w and w*s.
// (The pairwise 2x and the midpoint 0.5x cancel; near cancels in |m_i - m_j|.)
//
// R3: no smem, no cp.async, no barriers, no bounds checks (grid exact),
// fast reciprocal, all loads front-batched. One warp per ray, 4 elems/lane.

#define FULL 0xFFFFFFFFu

__global__ void __launch_bounds__(256) distortion_loss_kernel(
    const float* __restrict__ w,     // [R,128]
    const float* __restrict__ z,     // [R,129]
    const float* __restrict__ nearp, // [R]
    const float* __restrict__ farp,  // [R]
    float* __restrict__ out)         // [R]
{
    const int ray  = (blockIdx.x * 256 + threadIdx.x) >> 5;
    const int lane = threadIdx.x & 31;

    const float* wr = w + (size_t)ray * 128;
    const float* zr = z + (size_t)ray * 129 + 4 * lane;

    // ---- front-batched independent loads (max MLP) ----
    const float4 w4 = reinterpret_cast<const float4*>(wr)[lane];
    const float z0 = zr[0], z1 = zr[1], z2 = zr[2], z3 = zr[3], z4 = zr[4];
    const float nr = __ldg(nearp + ray);
    const float fr = __ldg(farp  + ray);

    const float wv0 = w4.x, wv1 = w4.y, wv2 = w4.z, wv3 = w4.w;

    // s = z_k + z_{k+1};  ws = w*s
    const float s0 = z0 + z1, s1 = z1 + z2, s2 = z2 + z3, s3 = z3 + z4;
    const float ws0 = wv0 * s0, ws1 = wv1 * s1, ws2 = wv2 * s2, ws3 = wv3 * s3;

    // lane-local inclusive sums
    const float cw1  = wv0 + wv1, cw2 = cw1 + wv2, tw  = cw2 + wv3;
    const float cws1 = ws0 + ws1, cws2 = cws1 + ws2, tws = cws2 + ws3;

    // warp inclusive scan of lane totals (shared ladder, predicated adds)
    float pw = tw, pws = tws;
    #pragma unroll
    for (int off = 1; off < 32; off <<= 1) {
        const float aw  = __shfl_up_sync(FULL, pw,  off);
        const float aws = __shfl_up_sync(FULL, pws, off);
        if (lane >= off) { pw += aw; pws += aws; }
    }
    const float bw  = pw  - tw;   // exclusive base: sum of w  over lanes < lane
    const float bws = pws - tws;  // exclusive base: sum of ws over lanes < lane

    // pairwise term: sum_k w_k*(s_k*W_<k - WS_<k), exclusive prefixes per element
    float acc;
    acc  = wv0 * fmaf(s0, bw,          -bws);
    acc += wv1 * fmaf(s1, bw + wv0,    -(bws + ws0));
    acc += wv2 * fmaf(s2, bw + cw1,    -(bws + cws1));
    acc += wv3 * fmaf(s3, bw + cw2,    -(bws + cws2));

    // (1/3) * w^2 * dz term
    float q;
    q  = wv0 * wv0 * (z1 - z0);
    q += wv1 * wv1 * (z2 - z1);
    q += wv2 * wv2 * (z3 - z2);
    q += wv3 * wv3 * (z4 - z3);
    acc = fmaf(q, (1.0f / 3.0f), acc);

    // warp reduction
    #pragma unroll
    for (int off = 16; off > 0; off >>= 1)
        acc += __shfl_down_sync(FULL, acc, off);

    if (lane == 0)
        out[ray] = acc * __fdividef(1.0f, fr - nr);
}

extern "C" void kernel_launch(void* const* d_in, const int* in_sizes, int n_in,
                              void* d_out, int out_size)
{
    const float* w   = (const float*)d_in[0]; // weights [R,128,1]
    const float* z   = (const float*)d_in[1]; // z_vals  [R,129]
    const float* nr  = (const float*)d_in[2]; // near    [R,1]
    const float* fr  = (const float*)d_in[3]; // far     [R,1]
    float*       out = (float*)d_out;         // [R,1]

    const int R = in_sizes[0] / 128;          // 8192
    distortion_loss_kernel<<<R / 8, 256>>>(w, z, nr, fr, out);
}

// round 4
// speedup vs baseline: 1.1276x; 1.0612x over previous
#include <cuda_runtime.h>
#include <cuda_bf16.h>

// DistortionLoss, O(N) via sorted-midpoint prefix sums.
//   s_k  = z_k + z_{k+1};  dz_k = z_{k+1} - z_k
//   loss = inv * [ sum_k w_k*(s_k*W_<k - WS_<k) + (1/3)*sum_k w_k^2*dz_k ]
// One warp per ray, 4 elements per lane.
//
// R4: z loaded as ALIGNED float4s + one broadcast quad; lane's 5 row elements
// reconstructed via shfl_down from the neighbor quad under a warp-uniform
// branch on the row misalignment r = (129*ray) & 3. This removes both the
// scalar-LDG replay cost (R1/R3: ~25 L1 wavefronts/warp) and the smem
// bank-conflict cost (R2) — z now costs 6 wavefronts per warp.

#define FULL 0xFFFFFFFFu

__global__ void __launch_bounds__(256) distortion_loss_kernel(
    const float*  __restrict__ w,     // [R,128]
    const float*  __restrict__ z,     // [R,129]
    const float*  __restrict__ nearp, // [R]
    const float*  __restrict__ farp,  // [R]
    float* __restrict__ out)          // [R]
{
    const int ray  = (blockIdx.x * 256 + threadIdx.x) >> 5;
    const int lane = threadIdx.x & 31;

    // ---- aligned-quad z load (z base is 16B-aligned from the harness) ----
    const int e0 = ray * 129;          // first element of this row
    const int qa = e0 >> 2;            // first aligned quad overlapping the row
    const int r  = e0 & 3;             // misalignment, uniform across the warp

    const float4* zq = reinterpret_cast<const float4*>(z);
    const float4 q  = zq[qa + lane];   // own aligned quad (5 wf)
    const float4 qx = zq[qa + 32];     // 33rd quad, same addr all lanes (1 wf)

    // w: one float4 per lane (rows are 512B, 16B-aligned)
    const float4 w4 = reinterpret_cast<const float4*>(w + (size_t)ray * 128)[lane];
    const float nr = __ldg(nearp + ray);
    const float fr = __ldg(farp  + ray);

    // ---- reconstruct row elements 4l..4l+4 (warp-uniform branch on r) ----
    float z0, z1, z2, z3, z4;
    const bool last = (lane == 31);
    if (r == 0) {
        z0 = q.x; z1 = q.y; z2 = q.z; z3 = q.w;
        float nx = __shfl_down_sync(FULL, q.x, 1);
        z4 = last ? qx.x : nx;
    } else if (r == 1) {
        z0 = q.y; z1 = q.z; z2 = q.w;
        float nx = __shfl_down_sync(FULL, q.x, 1);
        float ny = __shfl_down_sync(FULL, q.y, 1);
        z3 = last ? qx.x : nx;
        z4 = last ? qx.y : ny;
    } else if (r == 2) {
        z0 = q.z; z1 = q.w;
        float nx = __shfl_down_sync(FULL, q.x, 1);
        float ny = __shfl_down_sync(FULL, q.y, 1);
        float nz = __shfl_down_sync(FULL, q.z, 1);
        z2 = last ? qx.x : nx;
        z3 = last ? qx.y : ny;
        z4 = last ? qx.z : nz;
    } else {
        z0 = q.w;
        float nx = __shfl_down_sync(FULL, q.x, 1);
        float ny = __shfl_down_sync(FULL, q.y, 1);
        float nz = __shfl_down_sync(FULL, q.z, 1);
        float nw = __shfl_down_sync(FULL, q.w, 1);
        z1 = last ? qx.x : nx;
        z2 = last ? qx.y : ny;
        z3 = last ? qx.z : nz;
        z4 = last ? qx.w : nw;
    }

    const float wv0 = w4.x, wv1 = w4.y, wv2 = w4.z, wv3 = w4.w;

    // s = z_k + z_{k+1};  ws = w*s
    const float s0 = z0 + z1, s1 = z1 + z2, s2 = z2 + z3, s3 = z3 + z4;
    const float ws0 = wv0 * s0, ws1 = wv1 * s1, ws2 = wv2 * s2, ws3 = wv3 * s3;

    // lane-local inclusive sums
    const float cw1  = wv0 + wv1,  cw2  = cw1 + wv2,  tw  = cw2 + wv3;
    const float cws1 = ws0 + ws1,  cws2 = cws1 + ws2, tws = cws2 + ws3;

    // warp inclusive scan of lane totals (shared ladder)
    float pw = tw, pws = tws;
    #pragma unroll
    for (int off = 1; off < 32; off <<= 1) {
        const float aw  = __shfl_up_sync(FULL, pw,  off);
        const float aws = __shfl_up_sync(FULL, pws, off);
        if (lane >= off) { pw += aw; pws += aws; }
    }
    const float bw  = pw  - tw;   // exclusive base over lanes < lane
    const float bws = pws - tws;

    // pairwise term: sum_k w_k*(s_k*W_<k - WS_<k)
    float acc;
    acc  = wv0 * fmaf(s0, bw,         -bws);
    acc += wv1 * fmaf(s1, bw + wv0,   -(bws + ws0));
    acc += wv2 * fmaf(s2, bw + cw1,   -(bws + cws1));
    acc += wv3 * fmaf(s3, bw + cw2,   -(bws + cws2));

    // (1/3) * w^2 * dz term
    float qq;
    qq  = wv0 * wv0 * (z1 - z0);
    qq += wv1 * wv1 * (z2 - z1);
    qq += wv2 * wv2 * (z3 - z2);
    qq += wv3 * wv3 * (z4 - z3);
    acc = fmaf(qq, (1.0f / 3.0f), acc);

    // warp reduction
    #pragma unroll
    for (int off = 16; off > 0; off >>= 1)
        acc += __shfl_down_sync(FULL, acc, off);

    if (lane == 0)
        out[ray] = acc * __fdividef(1.0f, fr - nr);
}

extern "C" void kernel_launch(void* const* d_in, const int* in_sizes, int n_in,
                              void* d_out, int out_size)
{
    const float* w   = (const float*)d_in[0]; // weights [R,128,1]
    const float* z   = (const float*)d_in[1]; // z_vals  [R,129]
    const float* nr  = (const float*)d_in[2]; // near    [R,1]
    const float* fr  = (const float*)d_in[3]; // far     [R,1]
    float*       out = (float*)d_out;         // [R,1]

    const int R = in_sizes[0] / 128;          // 8192
    distortion_loss_kernel<<<R / 8, 256>>>(w, z, nr, fr, out);
}